// round 1
// baseline (speedup 1.0000x reference)
#include <cuda_runtime.h>
#include <math.h>

// ---------------------------------------------------------------------------
// Problem constants
// ---------------------------------------------------------------------------
namespace {
constexpr int TT = 128, BB = 32;
constexpr int POS_E = 64, WORD_E = 512, POS_H = 256, WORD_H = 1024;
constexpr int POS_V = 45, WORD_V = 32000;
constexpr int NTOK = TT * BB;  // 4096

// ---------------------------------------------------------------------------
// Device scratch (static globals; no allocation allowed)
// ---------------------------------------------------------------------------
__device__ float g_p_emb[NTOK * POS_E];            // 1 MB
__device__ float g_w_emb[NTOK * WORD_E];           // 8 MB
__device__ float g_pouts[NTOK * POS_H];            // 4 MB  (pos hidden per step)
__device__ float g_wouts[NTOK * WORD_H];           // 16 MB (word layer-1 hidden per step)
__device__ float g_wh0[2][BB * WORD_H];            // word layer-0 hidden ping-pong
__device__ float g_pc[2][BB * POS_H];              // cell-state ping-pongs
__device__ float g_wc0[2][BB * WORD_H];
__device__ float g_wc1[2][BB * WORD_H];
__device__ float g_zero[BB * WORD_H];              // zero h/x source for t=0
__device__ float g_gpart[8][BB * 4 * WORD_H];      // K-chunk partial gate sums (4 MB)
__device__ float g_wmid[NTOK * WORD_E];            // 8 MB
}  // namespace

// ---------------------------------------------------------------------------
// Init + embedding gather
// ---------------------------------------------------------------------------
__global__ void zero_init_kernel() {
    int i = blockIdx.x * blockDim.x + threadIdx.x;
    if (i < BB * WORD_H) {
        g_zero[i]   = 0.f;
        g_wc0[0][i] = 0.f;
        g_wc1[0][i] = 0.f;
    }
    if (i < BB * POS_H) g_pc[0][i] = 0.f;
}

__global__ void gather_kernel(const int* __restrict__ pos, const int* __restrict__ word,
                              const float* __restrict__ posW, const float* __restrict__ wordW) {
    int j = blockIdx.x * blockDim.x + threadIdx.x;
    const int total_w = NTOK * WORD_E;
    const int total_p = NTOK * POS_E;
    if (j < total_w) {
        int tok = j / WORD_E, d = j - tok * WORD_E;
        g_w_emb[j] = wordW[(size_t)word[tok] * WORD_E + d];
    }
    if (j < total_p) {
        int tok = j / POS_E, d = j - tok * POS_E;
        g_p_emb[j] = posW[(size_t)pos[tok] * POS_E + d];
    }
}

// ---------------------------------------------------------------------------
// LSTM cell = K-chunked partial GEMM + gate kernel
//   gate pre-activations g[b, 4H]; chunk c computes partial over its K slice.
//   Block: 32 batch-rows x 32 h-indices x 4 gates (128 output cols).
//   Thread: 4 rows x (1 h x 4 gates) = 16 accumulators.
// ---------------------------------------------------------------------------
struct Chunk { const float* x; const float* W; int ldx; int ldw; int koff; int klen; };
struct Chunks8 { Chunk c[8]; };

__global__ __launch_bounds__(256) void lstm_gemm_kernel(Chunks8 ch8, int H,
                                                        float* __restrict__ gpart) {
    __shared__ float xs[32][33];
    __shared__ float ws[128][33];
    const Chunk ch = ch8.c[blockIdx.y];
    float* out = gpart + (size_t)blockIdx.y * (BB * 4 * WORD_H);
    const int tid = threadIdx.x;
    const int rg = tid & 7;    // rows rg + 8j
    const int hl = tid >> 3;   // 0..31 (h index within tile)
    const int hBase = blockIdx.x * 32;

    float acc[4][4];
#pragma unroll
    for (int g = 0; g < 4; g++)
#pragma unroll
        for (int j = 0; j < 4; j++) acc[g][j] = 0.f;

    for (int kb = 0; kb < ch.klen; kb += 32) {
        // load x tile: 32 rows x 32 k (coalesced)
#pragma unroll
        for (int it = 0; it < 4; it++) {
            int idx = tid + it * 256;
            int row = idx >> 5, k = idx & 31;
            xs[row][k] = ch.x[(size_t)row * ch.ldx + kb + k];
        }
        // load W tile: 128 gate-rows x 32 k (coalesced)
#pragma unroll
        for (int it = 0; it < 16; it++) {
            int idx = tid + it * 256;
            int tr = idx >> 5, k = idx & 31;
            int g = tr >> 5, hh = tr & 31;
            ws[tr][k] = ch.W[(size_t)(g * H + hBase + hh) * ch.ldw + ch.koff + kb + k];
        }
        __syncthreads();
#pragma unroll
        for (int k = 0; k < 32; k++) {
            float xv[4];
#pragma unroll
            for (int j = 0; j < 4; j++) xv[j] = xs[rg + 8 * j][k];
#pragma unroll
            for (int g = 0; g < 4; g++) {
                float wv = ws[g * 32 + hl][k];
#pragma unroll
                for (int j = 0; j < 4; j++) acc[g][j] = fmaf(wv, xv[j], acc[g][j]);
            }
        }
        __syncthreads();
    }
#pragma unroll
    for (int g = 0; g < 4; g++)
#pragma unroll
        for (int j = 0; j < 4; j++) {
            int r = rg + 8 * j;
            out[(size_t)r * 4 * H + g * H + hBase + hl] = acc[g][j];
        }
}

__global__ void lstm_gate_kernel(int H, int nchunks,
                                 const float* __restrict__ bih, const float* __restrict__ bhh,
                                 const float* __restrict__ cin, float* __restrict__ cout,
                                 float* __restrict__ hout, const float* __restrict__ gpart) {
    int idx = blockIdx.x * blockDim.x + threadIdx.x;
    if (idx >= BB * H) return;
    int r = idx / H, h = idx - r * H;
    const size_t S = (size_t)BB * 4 * WORD_H;
    const float* gp = gpart + (size_t)r * 4 * H;
    float gi = 0.f, gf = 0.f, gg = 0.f, go = 0.f;
    for (int s = 0; s < nchunks; s++) {
        const float* p = gp + (size_t)s * S;
        gi += p[0 * H + h];
        gf += p[1 * H + h];
        gg += p[2 * H + h];
        go += p[3 * H + h];
    }
    gi += bih[0 * H + h] + bhh[0 * H + h];
    gf += bih[1 * H + h] + bhh[1 * H + h];
    gg += bih[2 * H + h] + bhh[2 * H + h];
    go += bih[3 * H + h] + bhh[3 * H + h];
    float i = 1.f / (1.f + expf(-gi));
    float f = 1.f / (1.f + expf(-gf));
    float g = tanhf(gg);
    float o = 1.f / (1.f + expf(-go));
    float c2 = f * cin[idx] + i * g;
    float h2 = o * tanhf(c2);
    cout[idx] = c2;
    hout[idx] = h2;
}

// ---------------------------------------------------------------------------
// Generic GEMM: C[m,n] = sum_k A[m,k]*W[n,k] + bias[n]
//   64x64 tile, 256 threads, 4x4 register tile per thread.
// ---------------------------------------------------------------------------
__global__ __launch_bounds__(256) void gemm_kernel(const float* __restrict__ A,
                                                   const float* __restrict__ W,
                                                   const float* __restrict__ bias,
                                                   float* __restrict__ C,
                                                   int M, int N, int K) {
    __shared__ float xs[64][33];
    __shared__ float ws[64][33];
    const int tid = threadIdx.x;
    const int rg = tid & 15;   // rows rg + 16j
    const int cs = tid >> 4;   // cols cs + 16i
    const int rBase = blockIdx.y * 64, cBase = blockIdx.x * 64;
    float acc[4][4];
#pragma unroll
    for (int i = 0; i < 4; i++)
#pragma unroll
        for (int j = 0; j < 4; j++) acc[i][j] = 0.f;

    for (int kb = 0; kb < K; kb += 32) {
#pragma unroll
        for (int it = 0; it < 8; it++) {
            int idx = tid + it * 256;
            int row = idx >> 5, k = idx & 31;
            xs[row][k] = A[(size_t)(rBase + row) * K + kb + k];
            ws[row][k] = W[(size_t)(cBase + row) * K + kb + k];
        }
        __syncthreads();
#pragma unroll
        for (int k = 0; k < 32; k++) {
            float xv[4], wv[4];
#pragma unroll
            for (int j = 0; j < 4; j++) xv[j] = xs[rg + 16 * j][k];
#pragma unroll
            for (int i = 0; i < 4; i++) wv[i] = ws[cs + 16 * i][k];
#pragma unroll
            for (int i = 0; i < 4; i++)
#pragma unroll
                for (int j = 0; j < 4; j++) acc[i][j] = fmaf(xv[j], wv[i], acc[i][j]);
        }
        __syncthreads();
    }
#pragma unroll
    for (int i = 0; i < 4; i++) {
        int c = cBase + cs + 16 * i;
        float b = bias ? bias[c] : 0.f;
#pragma unroll
        for (int j = 0; j < 4; j++)
            C[(size_t)(rBase + rg + 16 * j) * N + c] = acc[i][j] + b;
    }
}

// ---------------------------------------------------------------------------
// pos projection + log-softmax (one warp per (t,b) row; V=45, K=256)
// ---------------------------------------------------------------------------
__global__ void pos_proj_kernel(const float* __restrict__ Wp, const float* __restrict__ bp,
                                float* __restrict__ out) {
    const int row = blockIdx.x;
    const int lane = threadIdx.x;  // 32
    const bool has1 = (lane + 32 < POS_V);
    const float* x = g_pouts + (size_t)row * POS_H;
    float s0 = bp[lane];
    float s1 = has1 ? bp[lane + 32] : -INFINITY;
    const float* w0 = Wp + (size_t)lane * POS_H;
    const float* w1 = Wp + (size_t)(has1 ? lane + 32 : 0) * POS_H;
    for (int k = 0; k < POS_H; k++) {
        float xv = x[k];
        s0 = fmaf(xv, w0[k], s0);
        if (has1) s1 = fmaf(xv, w1[k], s1);
    }
    float m = fmaxf(s0, s1);
#pragma unroll
    for (int o = 16; o; o >>= 1) m = fmaxf(m, __shfl_xor_sync(0xffffffffu, m, o));
    float e = expf(s0 - m) + (has1 ? expf(s1 - m) : 0.f);
#pragma unroll
    for (int o = 16; o; o >>= 1) e += __shfl_xor_sync(0xffffffffu, e, o);
    float ls = m + logf(e);
    out[(size_t)row * POS_V + lane] = s0 - ls;
    if (has1) out[(size_t)row * POS_V + lane + 32] = s1 - ls;
}

// ---------------------------------------------------------------------------
// word log-softmax in place over 32000 (one block per row)
// ---------------------------------------------------------------------------
__global__ void word_softmax_kernel(float* __restrict__ logits) {
    __shared__ float red[8];
    const int row = blockIdx.x;
    float* p = logits + (size_t)row * WORD_V;
    const int tid = threadIdx.x;  // 256
    float m = -INFINITY;
    for (int i = tid; i < WORD_V; i += 256) m = fmaxf(m, p[i]);
#pragma unroll
    for (int o = 16; o; o >>= 1) m = fmaxf(m, __shfl_xor_sync(0xffffffffu, m, o));
    if ((tid & 31) == 0) red[tid >> 5] = m;
    __syncthreads();
    float M = red[0];
#pragma unroll
    for (int w = 1; w < 8; w++) M = fmaxf(M, red[w]);
    __syncthreads();
    float s = 0.f;
    for (int i = tid; i < WORD_V; i += 256) s += expf(p[i] - M);
#pragma unroll
    for (int o = 16; o; o >>= 1) s += __shfl_xor_sync(0xffffffffu, s, o);
    if ((tid & 31) == 0) red[tid >> 5] = s;
    __syncthreads();
    float S = 0.f;
#pragma unroll
    for (int w = 0; w < 8; w++) S += red[w];
    float ls = M + logf(S);
    for (int i = tid; i < WORD_V; i += 256) p[i] -= ls;
}

// ---------------------------------------------------------------------------
// Host side
// ---------------------------------------------------------------------------
static void add_seg(Chunks8& cc, int& n, const float* x, int ldx,
                    const float* W, int ldw, int koff, int klen) {
    while (klen > 0) {
        int c = klen > 256 ? 256 : klen;
        cc.c[n].x = x; cc.c[n].W = W; cc.c[n].ldx = ldx; cc.c[n].ldw = ldw;
        cc.c[n].koff = koff; cc.c[n].klen = c;
        n++;
        x += c; koff += c; klen -= c;
    }
}

extern "C" void kernel_launch(void* const* d_in, const int* in_sizes, int n_in,
                              void* d_out, int out_size) {
    (void)in_sizes; (void)n_in; (void)out_size;
    const int*   pos        = (const int*)d_in[0];
    const int*   word       = (const int*)d_in[1];
    const float* pos_emb_W  = (const float*)d_in[2];
    const float* word_emb_W = (const float*)d_in[3];
    const float* pos_Wih    = (const float*)d_in[4];
    const float* pos_Whh    = (const float*)d_in[5];
    const float* pos_bih    = (const float*)d_in[6];
    const float* pos_bhh    = (const float*)d_in[7];
    const float* w0_Wih     = (const float*)d_in[8];
    const float* w0_Whh     = (const float*)d_in[9];
    const float* w0_bih     = (const float*)d_in[10];
    const float* w0_bhh     = (const float*)d_in[11];
    const float* w1_Wih     = (const float*)d_in[12];
    const float* w1_Whh     = (const float*)d_in[13];
    const float* w1_bih     = (const float*)d_in[14];
    const float* w1_bhh     = (const float*)d_in[15];
    const float* pos_proj_W = (const float*)d_in[16];
    const float* pos_proj_b = (const float*)d_in[17];
    const float* wp1_W      = (const float*)d_in[18];
    const float* wp1_b      = (const float*)d_in[19];
    const float* wp2_b      = (const float*)d_in[20];
    float* out = (float*)d_out;

    float *p_emb, *w_emb, *pouts, *wouts, *wh0, *pc, *wc0, *wc1, *zerobuf, *gpart, *wmid;
    cudaGetSymbolAddress((void**)&p_emb, g_p_emb);
    cudaGetSymbolAddress((void**)&w_emb, g_w_emb);
    cudaGetSymbolAddress((void**)&pouts, g_pouts);
    cudaGetSymbolAddress((void**)&wouts, g_wouts);
    cudaGetSymbolAddress((void**)&wh0, g_wh0);
    cudaGetSymbolAddress((void**)&pc, g_pc);
    cudaGetSymbolAddress((void**)&wc0, g_wc0);
    cudaGetSymbolAddress((void**)&wc1, g_wc1);
    cudaGetSymbolAddress((void**)&zerobuf, g_zero);
    cudaGetSymbolAddress((void**)&gpart, g_gpart);
    cudaGetSymbolAddress((void**)&wmid, g_wmid);

    zero_init_kernel<<<(BB * WORD_H + 255) / 256, 256>>>();
    gather_kernel<<<(NTOK * WORD_E + 255) / 256, 256>>>(pos, word, pos_emb_W, word_emb_W);

    for (int t = 0; t < TT; t++) {
        const float* p_h_prev  = t ? pouts + (size_t)(t - 1) * BB * POS_H : zerobuf;
        const float* w1_h_prev = t ? wouts + (size_t)(t - 1) * BB * WORD_H : zerobuf;
        const float* wh0_prev  = t ? wh0 + (size_t)((t - 1) & 1) * BB * WORD_H : zerobuf;
        float* wh0_cur  = wh0 + (size_t)(t & 1) * BB * WORD_H;
        const float* x_pe = p_emb + (size_t)t * BB * POS_E;
        const float* x_we = w_emb + (size_t)t * BB * WORD_E;
        float* p_h_cur  = pouts + (size_t)t * BB * POS_H;
        float* w1_h_cur = wouts + (size_t)t * BB * WORD_H;
        const float* pc_in   = pc  + (size_t)(t & 1) * BB * POS_H;
        float*       pc_out  = pc  + (size_t)((t + 1) & 1) * BB * POS_H;
        const float* wc0_in  = wc0 + (size_t)(t & 1) * BB * WORD_H;
        float*       wc0_out = wc0 + (size_t)((t + 1) & 1) * BB * WORD_H;
        const float* wc1_in  = wc1 + (size_t)(t & 1) * BB * WORD_H;
        float*       wc1_out = wc1 + (size_t)((t + 1) & 1) * BB * WORD_H;

        // ---- pos cell: x = [p_emb(64) ; w_h1_prev(1024)], Whh K=256 ----
        {
            Chunks8 cc; int n = 0;
            add_seg(cc, n, x_pe,      POS_E,  pos_Wih, POS_E + WORD_H, 0,     POS_E);
            add_seg(cc, n, w1_h_prev, WORD_H, pos_Wih, POS_E + WORD_H, POS_E, WORD_H);
            add_seg(cc, n, p_h_prev,  POS_H,  pos_Whh, POS_H,          0,     POS_H);
            lstm_gemm_kernel<<<dim3(POS_H / 32, n), 256>>>(cc, POS_H, gpart);
            lstm_gate_kernel<<<(BB * POS_H + 255) / 256, 256>>>(
                POS_H, n, pos_bih, pos_bhh, pc_in, pc_out, p_h_cur, gpart);
        }
        // ---- word layer 0: x = [w_emb(512) ; p_h_cur(256)], Whh K=1024 ----
        {
            Chunks8 cc; int n = 0;
            add_seg(cc, n, x_we,     WORD_E, w0_Wih, WORD_E + POS_H, 0,      WORD_E);
            add_seg(cc, n, p_h_cur,  POS_H,  w0_Wih, WORD_E + POS_H, WORD_E, POS_H);
            add_seg(cc, n, wh0_prev, WORD_H, w0_Whh, WORD_H,         0,      WORD_H);
            lstm_gemm_kernel<<<dim3(WORD_H / 32, n), 256>>>(cc, WORD_H, gpart);
            lstm_gate_kernel<<<(BB * WORD_H + 255) / 256, 256>>>(
                WORD_H, n, w0_bih, w0_bhh, wc0_in, wc0_out, wh0_cur, gpart);
        }
        // ---- word layer 1: x = wh0_cur(1024), Whh K=1024 ----
        {
            Chunks8 cc; int n = 0;
            add_seg(cc, n, wh0_cur,   WORD_H, w1_Wih, WORD_H, 0, WORD_H);
            add_seg(cc, n, w1_h_prev, WORD_H, w1_Whh, WORD_H, 0, WORD_H);
            lstm_gemm_kernel<<<dim3(WORD_H / 32, n), 256>>>(cc, WORD_H, gpart);
            lstm_gate_kernel<<<(BB * WORD_H + 255) / 256, 256>>>(
                WORD_H, n, w1_bih, w1_bhh, wc1_in, wc1_out, w1_h_cur, gpart);
        }
    }

    // ---- pos projection + log-softmax -> out[0 : NTOK*POS_V] ----
    pos_proj_kernel<<<NTOK, 32>>>(pos_proj_W, pos_proj_b, out);

    // ---- word head: wmid = wouts @ wp1_W^T + b ; logits = wmid @ word_emb_W^T + b ----
    gemm_kernel<<<dim3(WORD_E / 64, NTOK / 64), 256>>>(wouts, wp1_W, wp1_b, wmid,
                                                       NTOK, WORD_E, WORD_H);
    float* wlp = out + (size_t)NTOK * POS_V;
    gemm_kernel<<<dim3(WORD_V / 64, NTOK / 64), 256>>>(wmid, word_emb_W, wp2_b, wlp,
                                                       NTOK, WORD_V, WORD_E);
    word_softmax_kernel<<<NTOK, 256>>>(wlp);
}